// round 4
// baseline (speedup 1.0000x reference)
#include <cuda_runtime.h>
#include <cstdint>
#include <math.h>
#include <mma.h>
using namespace nvcuda;

// ---------------- model constants ----------------
#define BATCH   512
#define S_LEN   215
#define DINP    36
#define DOB     4
#define DMODEL  144
#define DPE     16
#define DT      160
#define NHEAD   4
#define DH      40
#define NHID    128
#define FIN     860          // S_LEN * DOB
#define DFINAL  196          // DT + DINP
#define NROWS_GAT (BATCH*DINP)          // 18432
#define NROWS_TR  (S_LEN*BATCH)         // 110080

// ---------------- scratch (device globals; no allocation allowed) ----------------
__device__ float g_bufA[(size_t)BATCH*DINP*FIN];
__device__ float g_bufB[(size_t)BATCH*DINP*FIN];
__device__ float g_ps[NROWS_GAT];
__device__ float g_pd[NROWS_GAT];
__device__ float g_alpha1[(size_t)BATCH*DINP*DINP];
__device__ float g_alpha2[(size_t)BATCH*DINP*DINP];
__device__ float g_sq[BATCH];
__device__ float g_part[BATCH];
__device__ float g_x[(size_t)NROWS_TR*DT];
__device__ float g_qkv[(size_t)NROWS_TR*3*DT];
__device__ float g_att[(size_t)NROWS_TR*DT];
__device__ float g_tmp[(size_t)NROWS_TR*DT];
__device__ float g_ff[(size_t)NROWS_TR*NHID];
__device__ float g_feat[BATCH*DFINAL];

// ---------------- utility ----------------
__global__ void zero_kernel(float* p, int n) {
    int i = blockIdx.x*blockDim.x + threadIdx.x;
    if (i < n) p[i] = 0.f;
}

__device__ __forceinline__ void cp16(uint32_t dst, const void* src) {
    asm volatile("cp.async.cg.shared.global [%0], [%1], 16;\n" :: "r"(dst), "l"(src));
}
__device__ __forceinline__ void zero16(uint32_t dst) {
    asm volatile("st.shared.v4.b32 [%0], {%1,%1,%1,%1};\n" :: "r"(dst), "r"(0u));
}
__device__ __forceinline__ void cp_commit() {
    asm volatile("cp.async.commit_group;\n" ::: "memory");
}
__device__ __forceinline__ void cp_wait_all() {
    asm volatile("cp.async.wait_group 0;\n" ::: "memory");
}

// ---------------- TF32 tensor-core GEMM (double-buffered cp.async) ----------------
// C = act(A@B + bias + res). A: MxK row-major (M%128==0, K%4==0), B: KxN row-major (N%4==0).
// Tile 128x128x32, 256 threads = 8 warps (2x4), warp tile 64x32 = 4x2 m16n16k8 tf32.
#define GBM 128
#define GBN 128
#define GBK 32
#define ALD 36      // A tile ld (floats): rows rotate 4 banks -> <=2-way conflicts
#define BLD 132     // B tile ld
#define CLD 132     // epilogue staging ld
#define A_STG (GBM*ALD)          // 4608 floats
#define B_STG (GBK*BLD)          // 4224 floats
#define GEMM_SMEM ((2*(A_STG+B_STG) > GBM*CLD ? 2*(A_STG+B_STG) : GBM*CLD)*4)  // 70656 B

__global__ void tf32_gemm_kernel(const float* __restrict__ A, const float* __restrict__ B,
                                 float* __restrict__ C, int M, int N, int K,
                                 const float* __restrict__ bias,
                                 const float* __restrict__ res, int relu_flag)
{
    extern __shared__ float sm[];
    float* As0 = sm;
    float* As1 = sm + A_STG;
    float* Bs0 = sm + 2*A_STG;
    float* Bs1 = sm + 2*A_STG + B_STG;

    int tid = threadIdx.x;
    int warpId = tid >> 5;
    int wr = warpId >> 2;           // 0..1
    int wc = warpId & 3;            // 0..3
    int row0 = blockIdx.y*GBM, col0 = blockIdx.x*GBN;

    wmma::fragment<wmma::accumulator,16,16,8,float> cf[4][2];
    #pragma unroll
    for (int i=0;i<4;i++)
      #pragma unroll
      for (int j=0;j<2;j++) wmma::fill_fragment(cf[i][j], 0.f);

    const int nIter = (K + GBK - 1) / GBK;

    // stage loader: A tile 128x32 (row-major ld ALD), B tile 32x128 (ld BLD)
    auto load_stage = [&](float* as, float* bs, int k0) {
        #pragma unroll
        for (int i = tid; i < GBM*GBK/4; i += 256) {
            int r = i >> 3, c4 = (i & 7)*4;
            int gc = k0 + c4;
            uint32_t dst = (uint32_t)__cvta_generic_to_shared(&as[r*ALD + c4]);
            if (gc < K) cp16(dst, &A[(size_t)(row0+r)*K + gc]);
            else        zero16(dst);
        }
        #pragma unroll
        for (int i = tid; i < GBK*GBN/4; i += 256) {
            int kr = i >> 5, cc = (i & 31)*4;
            int gr = k0 + kr, gc = col0 + cc;
            uint32_t dst = (uint32_t)__cvta_generic_to_shared(&bs[kr*BLD + cc]);
            if (gr < K && gc < N) cp16(dst, &B[(size_t)gr*N + gc]);
            else                  zero16(dst);
        }
        cp_commit();
    };

    load_stage(As0, Bs0, 0);

    for (int it = 0; it < nIter; it++) {
        cp_wait_all();
        __syncthreads();
        float* as = (it & 1) ? As1 : As0;
        float* bs = (it & 1) ? Bs1 : Bs0;
        if (it + 1 < nIter)
            load_stage((it & 1) ? As0 : As1, (it & 1) ? Bs0 : Bs1, (it+1)*GBK);

        #pragma unroll
        for (int ks = 0; ks < GBK; ks += 8) {
            wmma::fragment<wmma::matrix_a,16,16,8,wmma::precision::tf32,wmma::row_major> af[4];
            wmma::fragment<wmma::matrix_b,16,16,8,wmma::precision::tf32,wmma::row_major> bf[2];
            #pragma unroll
            for (int fr=0; fr<4; fr++) {
                wmma::load_matrix_sync(af[fr], &as[(wr*64 + fr*16)*ALD + ks], ALD);
                #pragma unroll
                for (int t=0;t<af[fr].num_elements;t++) af[fr].x[t] = wmma::__float_to_tf32(af[fr].x[t]);
            }
            #pragma unroll
            for (int fc=0; fc<2; fc++) {
                wmma::load_matrix_sync(bf[fc], &bs[ks*BLD + wc*32 + fc*16], BLD);
                #pragma unroll
                for (int t=0;t<bf[fc].num_elements;t++) bf[fc].x[t] = wmma::__float_to_tf32(bf[fc].x[t]);
            }
            #pragma unroll
            for (int fr=0; fr<4; fr++)
              #pragma unroll
              for (int fc=0; fc<2; fc++)
                wmma::mma_sync(cf[fr][fc], af[fr], bf[fc], cf[fr][fc]);
        }
        __syncthreads();
    }

    // epilogue: stage to smem (reuses tile memory), fused bias/res/relu
    float* Cs = sm;
    #pragma unroll
    for (int fr=0; fr<4; fr++)
      #pragma unroll
      for (int fc=0; fc<2; fc++)
        wmma::store_matrix_sync(&Cs[(wr*64 + fr*16)*CLD + wc*32 + fc*16],
                                cf[fr][fc], CLD, wmma::mem_row_major);
    __syncthreads();

    for (int i = tid; i < GBM*GBN; i += 256) {
        int r = i >> 7, c = i & 127;
        int gc = col0 + c;
        if (gc >= N) continue;
        float v = Cs[r*CLD + c];
        if (bias) v += bias[gc];
        size_t off = (size_t)(row0 + r)*N + gc;
        if (res)  v += res[off];
        if (relu_flag) v = fmaxf(v, 0.f);
        C[off] = v;
    }
}

// ---------------- GAT ----------------
__global__ void build_x_kernel(const float* __restrict__ src, const float* __restrict__ R_u)
{
    size_t n = (size_t)blockIdx.x*blockDim.x + threadIdx.x;
    const size_t total = (size_t)BATCH*DINP*FIN;
    if (n >= total) return;
    int c = (int)(n % FIN);
    int i = (int)((n / FIN) % DINP);
    int b = (int)(n / ((size_t)FIN*DINP));
    int s = c >> 2, o = c & 3;
    float v = src[((size_t)s*BATCH + b)*(2*DINP) + i];
    g_bufA[n] = fmaxf(v * R_u[i*4+o], 0.f);
}

__global__ void psd_kernel(const float* __restrict__ XP,
                           const float* __restrict__ a_s, const float* __restrict__ a_d)
{
    int row = blockIdx.x;
    const float* x = XP + (size_t)row*FIN;
    int t = threadIdx.x;
    float s1=0.f, s2=0.f;
    for (int c=t; c<FIN; c+=256) { float v=x[c]; s1 += v*a_s[c]; s2 += v*a_d[c]; }
    __shared__ float r1[256], r2[256];
    r1[t]=s1; r2[t]=s2; __syncthreads();
    for (int o=128;o>0;o>>=1){ if(t<o){r1[t]+=r1[t+o]; r2[t]+=r2[t+o];} __syncthreads(); }
    if (t==0){ g_ps[row]=r1[0]; g_pd[row]=r2[0]; }
}

__global__ void alpha_kernel(const float* __restrict__ edge, float* __restrict__ alpha)
{
    int b = blockIdx.x;
    int i = threadIdx.x;
    if (i >= DINP) return;
    const float* psb = g_ps + b*DINP;
    float pdi = g_pd[b*DINP+i];
    float e[DINP];
    float m = -1e30f;
    #pragma unroll
    for (int j=0;j<DINP;j++){
        float v = pdi + psb[j];
        v = (v > 0.f) ? v : 0.2f*v;
        e[j]=v; m = fmaxf(m,v);
    }
    float l=0.f;
    #pragma unroll
    for (int j=0;j<DINP;j++){ float w=expf(e[j]-m); e[j]=w; l+=w; }
    float inv = 1.f/l;
    size_t base = ((size_t)b*DINP + i)*DINP;
    #pragma unroll
    for (int j=0;j<DINP;j++){
        float a = e[j]*inv;
        if (edge) a *= edge[base+j];
        alpha[base+j] = a;
    }
}

__global__ void gat_agg_kernel(const float* __restrict__ alpha, const float* __restrict__ XP,
                               float* __restrict__ H)
{
    int b = blockIdx.x;
    __shared__ float al[DINP*DINP];
    for (int i=threadIdx.x;i<DINP*DINP;i+=blockDim.x) al[i]=alpha[(size_t)b*DINP*DINP+i];
    __syncthreads();
    const float* xp = XP + (size_t)b*DINP*FIN;
    float* hb = H + (size_t)b*DINP*FIN;
    for (int idx=threadIdx.x; idx<DINP*FIN; idx+=blockDim.x){
        int i = idx/FIN, c = idx%FIN;
        float s=0.f;
        #pragma unroll 6
        for (int j=0;j<DINP;j++) s += al[i*DINP+j]*xp[(size_t)j*FIN+c];
        hb[idx]=s;
    }
}

__global__ void sq_kernel(const float* __restrict__ A)
{
    int b = blockIdx.x; int t = threadIdx.x;
    float s=0.f;
    for (int i=t;i<DINP*DINP;i+=256){ float v=A[(size_t)b*DINP*DINP+i]; s+=v*v; }
    __shared__ float r[256];
    r[t]=s; __syncthreads();
    for (int o=128;o>0;o>>=1){ if(t<o) r[t]+=r[t+o]; __syncthreads(); }
    if (t==0) g_sq[b]=r[0];
}

__global__ void dist_kernel(const float* __restrict__ A)
{
    int i = blockIdx.x; int t = threadIdx.x;
    __shared__ float Ai[DINP*DINP];
    for (int c=t;c<DINP*DINP;c+=256) Ai[c]=A[(size_t)i*DINP*DINP+c];
    __syncthreads();
    float local=0.f;
    for (int j=t;j<BATCH;j+=256){
        const float* Aj = A + (size_t)j*DINP*DINP;
        float dot=0.f;
        for (int c=0;c<DINP*DINP;c++) dot += Ai[c]*Aj[c];
        float d2 = g_sq[i]+g_sq[j]-2.f*dot;
        d2 = fmaxf(d2, 0.f);
        local += sqrtf(d2 + 1e-12f);
    }
    __shared__ float r[256];
    r[t]=local; __syncthreads();
    for (int o=128;o>0;o>>=1){ if(t<o) r[t]+=r[t+o]; __syncthreads(); }
    if (t==0) g_part[i]=r[0];
}

__global__ void fin_dist_kernel(float* __restrict__ out, int out_size)
{
    if (threadIdx.x==0){
        float s=0.f;
        for (int i=0;i<BATCH;i++) s += g_part[i];
        if (out_size > BATCH*2) out[BATCH*2] = s / ((float)BATCH*(float)BATCH);
    }
}

// ---------------- transformer input ----------------
__global__ void build_out_kernel(const float* __restrict__ times)
{
    size_t n = (size_t)blockIdx.x*blockDim.x + threadIdx.x;
    const size_t total = (size_t)NROWS_TR*DT;
    if (n >= total) return;
    int d = (int)(n % DT);
    int b = (int)((n / DT) % BATCH);
    int s = (int)(n / ((size_t)DT*BATCH));
    float v;
    if (d < DMODEL) {
        v = g_bufA[((size_t)b*DINP + (d>>2))*FIN + s*4 + (d&3)];
    } else {
        int k = d - DMODEL;
        float tv = times[(size_t)s*BATCH + b];
        int kk = (k < 8) ? k : k-8;
        float ts = powf(215.0f, (float)kk/7.0f) * 100.0f;
        float sc = tv / ts;
        v = (k < 8) ? sinf(sc) : cosf(sc);
    }
    g_x[n] = v;
}

// ---------------- attention (K and V fully resident in smem) ----------------
#define ATTN_SMEM (2*S_LEN*DH*4)   // 68800 B
__global__ void attn_kernel(const float* __restrict__ qkv, const int* __restrict__ lengths,
                            float* __restrict__ out)
{
    extern __shared__ float smA[];
    float* Ks = smA;
    float* Vs = smA + S_LEN*DH;
    int b = blockIdx.x, h = blockIdx.y;
    int len = lengths[b];
    for (int i = threadIdx.x; i < S_LEN*DH; i += blockDim.x) {
        int t = i / DH, d = i % DH;
        size_t base = ((size_t)t*BATCH + b)*(3*DT) + h*DH + d;
        Ks[i] = qkv[base + DT];
        Vs[i] = qkv[base + 2*DT];
    }
    __syncthreads();
    int s = threadIdx.x;
    if (s >= S_LEN) return;
    float q[DH];
    {
        size_t qb = ((size_t)s*BATCH + b)*(3*DT) + h*DH;
        #pragma unroll
        for (int d=0; d<DH; d++) q[d] = qkv[qb + d];
    }
    const float scale = rsqrtf((float)DH);
    float m = -1e30f;
    for (int t=0; t<len; t++) {
        float sc = 0.f;
        #pragma unroll
        for (int d=0; d<DH; d++) sc += q[d]*Ks[t*DH+d];
        m = fmaxf(m, sc*scale);
    }
    float l = 0.f;
    float acc[DH];
    #pragma unroll
    for (int d=0; d<DH; d++) acc[d]=0.f;
    for (int t=0; t<len; t++) {
        float sc = 0.f;
        #pragma unroll
        for (int d=0; d<DH; d++) sc += q[d]*Ks[t*DH+d];
        float w = expf(sc*scale - m);
        l += w;
        #pragma unroll
        for (int d=0; d<DH; d++) acc[d] += w*Vs[t*DH+d];
    }
    float inv = 1.f/l;
    size_t ob = ((size_t)s*BATCH + b)*DT + h*DH;
    #pragma unroll
    for (int d=0; d<DH; d++) out[ob + d] = acc[d]*inv;
}

// ---------------- layernorm ----------------
__global__ void ln_kernel(const float* __restrict__ x, float* __restrict__ y,
                          const float* __restrict__ g, const float* __restrict__ bta)
{
    int row = blockIdx.x;
    const float* xr = x + (size_t)row*DT;
    int t = threadIdx.x;
    float v = xr[t];
    __shared__ float s1[DT], s2[DT];
    s1[t]=v; s2[t]=v*v; __syncthreads();
    if (t < 32) {
        float a=0.f, q=0.f;
        for (int i=t;i<DT;i+=32){ a+=s1[i]; q+=s2[i]; }
        for (int o=16;o>0;o>>=1){ a+=__shfl_down_sync(0xffffffff,a,o); q+=__shfl_down_sync(0xffffffff,q,o); }
        if (t==0){ s1[0]=a; s2[0]=q; }
    }
    __syncthreads();
    float mean = s1[0]/(float)DT;
    float var  = s2[0]/(float)DT - mean*mean;
    y[(size_t)row*DT + t] = (v-mean)*rsqrtf(var+1e-5f)*g[t] + bta[t];
}

// ---------------- pooled features + static embedding ----------------
__global__ void agg_emb_kernel(const int* __restrict__ lengths,
                               const float* __restrict__ statics,
                               const float* __restrict__ emb_w, const float* __restrict__ emb_b)
{
    int b = blockIdx.x; int d = threadIdx.x;
    int len = lengths[b];
    if (d < DT) {
        float s = 0.f;
        for (int t=0;t<len;t++) s += g_x[((size_t)t*BATCH + b)*DT + d];
        g_feat[b*DFINAL+d] = s / ((float)len + 1.0f);
    } else if (d < DFINAL) {
        int j = d - DT;
        float s = emb_b[j];
        #pragma unroll
        for (int r=0;r<9;r++) s += statics[b*9+r]*emb_w[r*DINP+j];
        g_feat[b*DFINAL+d] = s;
    }
}

// ---------------- final MLP ----------------
__global__ void mlp_kernel(const float* __restrict__ w1, const float* __restrict__ b1,
                           const float* __restrict__ w2, const float* __restrict__ b2,
                           float* __restrict__ out)
{
    int b = blockIdx.x; int t = threadIdx.x;
    __shared__ float f[DFINAL], hd[DFINAL];
    f[t] = g_feat[b*DFINAL+t];
    __syncthreads();
    float s = b1[t];
    for (int r=0;r<DFINAL;r++) s += f[r]*w1[r*DFINAL+t];
    hd[t] = fmaxf(s, 0.f);
    __syncthreads();
    if (t < 2) {
        float s2 = b2[t];
        for (int r=0;r<DFINAL;r++) s2 += hd[r]*w2[r*2+t];
        out[b*2+t] = s2;
    }
}

// ---------------- launch ----------------
extern "C" void kernel_launch(void* const* d_in, const int* in_sizes, int n_in,
                              void* d_out, int out_size)
{
    const float* src    = (const float*)d_in[0];
    const float* statics= (const float*)d_in[1];
    const float* times  = (const float*)d_in[2];
    const int*   lengths= (const int*)d_in[3];
    const float* R_u    = (const float*)d_in[4];
    const float* emb_w  = (const float*)d_in[5];
    const float* emb_b  = (const float*)d_in[6];
    const float* W1     = (const float*)d_in[7];
    const float* a1_s   = (const float*)d_in[8];
    const float* a1_d   = (const float*)d_in[9];
    const float* W2     = (const float*)d_in[10];
    const float* a2_s   = (const float*)d_in[11];
    const float* a2_d   = (const float*)d_in[12];
    const float* attn_in_w  = (const float*)d_in[13];
    const float* attn_in_b  = (const float*)d_in[14];
    const float* attn_out_w = (const float*)d_in[15];
    const float* attn_out_b = (const float*)d_in[16];
    const float* ff1_w  = (const float*)d_in[17];
    const float* ff1_b  = (const float*)d_in[18];
    const float* ff2_w  = (const float*)d_in[19];
    const float* ff2_b  = (const float*)d_in[20];
    const float* ln1_g  = (const float*)d_in[21];
    const float* ln1_b  = (const float*)d_in[22];
    const float* ln2_g  = (const float*)d_in[23];
    const float* ln2_b  = (const float*)d_in[24];
    const float* mlp1_w = (const float*)d_in[25];
    const float* mlp1_b = (const float*)d_in[26];
    const float* mlp2_w = (const float*)d_in[27];
    const float* mlp2_b = (const float*)d_in[28];
    float* out = (float*)d_out;

    float *bufA, *bufB, *al1, *al2, *x, *qkv, *att, *tmp, *ff;
    cudaGetSymbolAddress((void**)&bufA, g_bufA);
    cudaGetSymbolAddress((void**)&bufB, g_bufB);
    cudaGetSymbolAddress((void**)&al1,  g_alpha1);
    cudaGetSymbolAddress((void**)&al2,  g_alpha2);
    cudaGetSymbolAddress((void**)&x,    g_x);
    cudaGetSymbolAddress((void**)&qkv,  g_qkv);
    cudaGetSymbolAddress((void**)&att,  g_att);
    cudaGetSymbolAddress((void**)&tmp,  g_tmp);
    cudaGetSymbolAddress((void**)&ff,   g_ff);

    static bool attr_done = false;
    if (!attr_done) {
        cudaFuncSetAttribute(tf32_gemm_kernel,
                             cudaFuncAttributeMaxDynamicSharedMemorySize, GEMM_SMEM);
        cudaFuncSetAttribute(attn_kernel,
                             cudaFuncAttributeMaxDynamicSharedMemorySize, ATTN_SMEM);
        attr_done = true;
    }

    zero_kernel<<<(out_size+255)/256, 256>>>(out, out_size);

    // ----- GAT -----
    {
        size_t nx = (size_t)BATCH*DINP*FIN;
        build_x_kernel<<<(unsigned)((nx+255)/256), 256>>>(src, R_u);
        dim3 gg((FIN+GBN-1)/GBN, NROWS_GAT/GBM);
        tf32_gemm_kernel<<<gg,256,GEMM_SMEM>>>(bufA, W1, bufB, NROWS_GAT, FIN, FIN, nullptr, nullptr, 0);
        psd_kernel<<<NROWS_GAT,256>>>(bufB, a1_s, a1_d);
        alpha_kernel<<<BATCH,64>>>(nullptr, al1);
        gat_agg_kernel<<<BATCH,256>>>(al1, bufB, bufA);
        tf32_gemm_kernel<<<gg,256,GEMM_SMEM>>>(bufA, W2, bufB, NROWS_GAT, FIN, FIN, nullptr, nullptr, 0);
        psd_kernel<<<NROWS_GAT,256>>>(bufB, a2_s, a2_d);
        alpha_kernel<<<BATCH,64>>>(al1, al2);
        gat_agg_kernel<<<BATCH,256>>>(al2, bufB, bufA);
        sq_kernel<<<BATCH,256>>>(al2);
        dist_kernel<<<BATCH,256>>>(al2);
        fin_dist_kernel<<<1,32>>>(out, out_size);
    }

    // ----- transformer -----
    {
        size_t no = (size_t)NROWS_TR*DT;
        build_out_kernel<<<(unsigned)((no+255)/256), 256>>>(times);
        for (int l=0; l<2; l++) {
            dim3 gq((3*DT+GBN-1)/GBN, NROWS_TR/GBM);
            tf32_gemm_kernel<<<gq,256,GEMM_SMEM>>>(x, attn_in_w + (size_t)l*DT*3*DT, qkv,
                                     NROWS_TR, 3*DT, DT, attn_in_b + l*3*DT, nullptr, 0);
            attn_kernel<<<dim3(BATCH,NHEAD),256,ATTN_SMEM>>>(qkv, lengths, att);
            dim3 gp((DT+GBN-1)/GBN, NROWS_TR/GBM);
            tf32_gemm_kernel<<<gp,256,GEMM_SMEM>>>(att, attn_out_w + (size_t)l*DT*DT, tmp,
                                     NROWS_TR, DT, DT, attn_out_b + l*DT, x, 0);
            ln_kernel<<<NROWS_TR,DT>>>(tmp, x, ln1_g + l*DT, ln1_b + l*DT);
            dim3 gf1((NHID+GBN-1)/GBN, NROWS_TR/GBM);
            tf32_gemm_kernel<<<gf1,256,GEMM_SMEM>>>(x, ff1_w + (size_t)l*DT*NHID, ff,
                                      NROWS_TR, NHID, DT, ff1_b + l*NHID, nullptr, 1);
            dim3 gf2((DT+GBN-1)/GBN, NROWS_TR/GBM);
            tf32_gemm_kernel<<<gf2,256,GEMM_SMEM>>>(ff, ff2_w + (size_t)l*NHID*DT, tmp,
                                      NROWS_TR, DT, NHID, ff2_b + l*DT, x, 0);
            ln_kernel<<<NROWS_TR,DT>>>(tmp, x, ln2_g + l*DT, ln2_b + l*DT);
        }
    }

    // ----- head -----
    agg_emb_kernel<<<BATCH,DFINAL>>>(lengths, statics, emb_w, emb_b);
    mlp_kernel<<<BATCH,DFINAL>>>(mlp1_w, mlp1_b, mlp2_w, mlp2_b, out);
}

// round 6
// speedup vs baseline: 2.1262x; 2.1262x over previous
#include <cuda_runtime.h>
#include <cuda_fp16.h>
#include <cstdint>
#include <math.h>
#include <mma.h>
using namespace nvcuda;

// ---------------- model constants ----------------
#define BATCH   512
#define S_LEN   215
#define DINP    36
#define DOB     4
#define DMODEL  144
#define DPE     16
#define DT      160
#define NHEAD   4
#define DH      40
#define NHID    128
#define FIN     860          // S_LEN * DOB
#define DFINAL  196          // DT + DINP
#define NROWS_GAT (BATCH*DINP)          // 18432
#define NROWS_TR  (S_LEN*BATCH)         // 110080

// ---------------- scratch (device globals; no allocation allowed) ----------------
__device__ float g_bufA[(size_t)BATCH*DINP*FIN];
__device__ float g_bufB[(size_t)BATCH*DINP*FIN];
__device__ float g_ps[NROWS_GAT];
__device__ float g_pd[NROWS_GAT];
__device__ float g_alpha1[(size_t)BATCH*DINP*DINP];
__device__ float g_alpha2[(size_t)BATCH*DINP*DINP];
__device__ float g_sq[BATCH];
__device__ float g_part[BATCH];
__device__ float g_x[(size_t)NROWS_TR*DT];
__device__ float g_qkv[(size_t)NROWS_TR*3*DT];
__device__ float g_att[(size_t)NROWS_TR*DT];
__device__ float g_tmp[(size_t)NROWS_TR*DT];
__device__ float g_ff[(size_t)NROWS_TR*NHID];
__device__ float g_feat[BATCH*DFINAL];

// ---------------- utility ----------------
__global__ void zero_kernel(float* p, int n) {
    int i = blockIdx.x*blockDim.x + threadIdx.x;
    if (i < n) p[i] = 0.f;
}

// ---------------- FP16 tensor-core GEMM ----------------
// C = act(A@B + bias + res). A: MxK fp32 row-major (M%128==0, K%4==0),
// B: KxN fp32 row-major. Operands converted to fp16 in smem; fp32 accumulate.
// Tile 128x128x32, 256 thr = 8 warps (2x4), warp tile 64x32 = 4x2 m16n16k16.
#define GBK 32
#define ALD2 40    // smem ld in halves (80B rows: 16B-aligned, bank-rotating)
#define WLD 20     // per-warp epilogue staging ld (floats)

__global__ void __launch_bounds__(256, 2)
hgemm_kernel(const float* __restrict__ A, const float* __restrict__ B,
             float* __restrict__ C, int M, int N, int K,
             const float* __restrict__ bias,
             const float* __restrict__ res, int relu_flag)
{
    __shared__ __half As[128*ALD2];       // 10240 B
    __shared__ __half Bs[128*ALD2];       // 10240 B  (row n holds K-slice: col-major B)
    __shared__ float  Wb[8][16*WLD];      // 10240 B  per-warp epilogue staging

    int tid = threadIdx.x;
    int warpId = tid >> 5, lane = tid & 31;
    int wr = warpId >> 2;     // 0..1 -> row offset wr*64
    int wc = warpId & 3;      // 0..3 -> col offset wc*32
    int row0 = blockIdx.y*128, col0 = blockIdx.x*128;

    wmma::fragment<wmma::accumulator,16,16,16,float> cf[4][2];
    #pragma unroll
    for (int i=0;i<4;i++)
      #pragma unroll
      for (int j=0;j<2;j++) wmma::fill_fragment(cf[i][j], 0.f);

    const int nIter = (K + GBK - 1) / GBK;

    for (int it = 0; it < nIter; it++) {
        int k0 = it*GBK;
        __syncthreads();   // protect previous iteration's fragment reads

        // ---- stage A: 128 rows x 32 halves; 2 chunks of 8 per thread ----
        #pragma unroll
        for (int c = 0; c < 2; c++) {
            int ci = tid + c*256;           // 0..511
            int r = ci >> 2, c8 = ci & 3;
            int gk = k0 + c8*8;
            const float* src = A + (size_t)(row0+r)*K + gk;
            __half h[8];
            if (gk + 8 <= K) {
                float4 v0 = *(const float4*)src;
                float4 v1 = *(const float4*)(src+4);
                h[0]=__float2half(v0.x); h[1]=__float2half(v0.y);
                h[2]=__float2half(v0.z); h[3]=__float2half(v0.w);
                h[4]=__float2half(v1.x); h[5]=__float2half(v1.y);
                h[6]=__float2half(v1.z); h[7]=__float2half(v1.w);
            } else {
                #pragma unroll
                for (int e = 0; e < 8; e++)
                    h[e] = __float2half((gk+e < K) ? src[e] : 0.f);
            }
            *(uint4*)&As[r*ALD2 + c8*8] = *(uint4*)h;
        }

        // ---- stage B transposed: Bs[n][k] = B[k0+k][col0+n]; coalesced reads ----
        #pragma unroll
        for (int kk = 0; kk < 4; kk++) {
            int kr = warpId + kk*8;         // 0..31
            int gkr = k0 + kr;
            bool kok = (gkr < K);
            #pragma unroll
            for (int nc2 = 0; nc2 < 4; nc2++) {
                int n = nc2*32 + lane;
                int gc = col0 + n;
                float v = (kok && gc < N) ? B[(size_t)gkr*N + gc] : 0.f;
                Bs[n*ALD2 + kr] = __float2half(v);
            }
        }
        __syncthreads();

        // ---- MMA: 2 k-steps of 16 ----
        #pragma unroll
        for (int ks = 0; ks < GBK; ks += 16) {
            wmma::fragment<wmma::matrix_a,16,16,16,__half,wmma::row_major> af[4];
            wmma::fragment<wmma::matrix_b,16,16,16,__half,wmma::col_major> bf[2];
            #pragma unroll
            for (int fr=0; fr<4; fr++)
                wmma::load_matrix_sync(af[fr], &As[(wr*64 + fr*16)*ALD2 + ks], ALD2);
            #pragma unroll
            for (int fc=0; fc<2; fc++)
                wmma::load_matrix_sync(bf[fc], &Bs[(wc*32 + fc*16)*ALD2 + ks], ALD2);
            #pragma unroll
            for (int fr=0; fr<4; fr++)
              #pragma unroll
              for (int fc=0; fc<2; fc++)
                wmma::mma_sync(cf[fr][fc], af[fr], bf[fc], cf[fr][fc]);
        }
    }

    // ---- epilogue: per-warp staging, fused bias/res/relu ----
    float* wbuf = Wb[warpId];
    #pragma unroll
    for (int fr=0; fr<4; fr++) {
        #pragma unroll
        for (int fc=0; fc<2; fc++) {
            wmma::store_matrix_sync(wbuf, cf[fr][fc], WLD, wmma::mem_row_major);
            __syncwarp();
            int rb = row0 + wr*64 + fr*16;
            int cb = col0 + wc*32 + fc*16;
            #pragma unroll
            for (int i = lane; i < 256; i += 32) {
                int r = i >> 4, c = i & 15;
                int gc = cb + c;
                if (gc < N) {
                    float v = wbuf[r*WLD + c];
                    if (bias) v += bias[gc];
                    size_t off = (size_t)(rb + r)*N + gc;
                    if (res)  v += res[off];
                    if (relu_flag) v = fmaxf(v, 0.f);
                    C[off] = v;
                }
            }
            __syncwarp();
        }
    }
}

// ---------------- GAT ----------------
__global__ void build_x_kernel(const float* __restrict__ src, const float* __restrict__ R_u)
{
    size_t n = (size_t)blockIdx.x*blockDim.x + threadIdx.x;
    const size_t total = (size_t)BATCH*DINP*FIN;
    if (n >= total) return;
    int c = (int)(n % FIN);
    int i = (int)((n / FIN) % DINP);
    int b = (int)(n / ((size_t)FIN*DINP));
    int s = c >> 2, o = c & 3;
    float v = src[((size_t)s*BATCH + b)*(2*DINP) + i];
    g_bufA[n] = fmaxf(v * R_u[i*4+o], 0.f);
}

__global__ void psd_kernel(const float* __restrict__ XP,
                           const float* __restrict__ a_s, const float* __restrict__ a_d)
{
    int row = blockIdx.x;
    const float* x = XP + (size_t)row*FIN;
    int t = threadIdx.x;
    float s1=0.f, s2=0.f;
    for (int c=t; c<FIN; c+=256) { float v=x[c]; s1 += v*a_s[c]; s2 += v*a_d[c]; }
    __shared__ float r1[256], r2[256];
    r1[t]=s1; r2[t]=s2; __syncthreads();
    for (int o=128;o>0;o>>=1){ if(t<o){r1[t]+=r1[t+o]; r2[t]+=r2[t+o];} __syncthreads(); }
    if (t==0){ g_ps[row]=r1[0]; g_pd[row]=r2[0]; }
}

__global__ void alpha_kernel(const float* __restrict__ edge, float* __restrict__ alpha)
{
    int b = blockIdx.x;
    int i = threadIdx.x;
    if (i >= DINP) return;
    const float* psb = g_ps + b*DINP;
    float pdi = g_pd[b*DINP+i];
    float e[DINP];
    float m = -1e30f;
    #pragma unroll
    for (int j=0;j<DINP;j++){
        float v = pdi + psb[j];
        v = (v > 0.f) ? v : 0.2f*v;
        e[j]=v; m = fmaxf(m,v);
    }
    float l=0.f;
    #pragma unroll
    for (int j=0;j<DINP;j++){ float w=expf(e[j]-m); e[j]=w; l+=w; }
    float inv = 1.f/l;
    size_t base = ((size_t)b*DINP + i)*DINP;
    #pragma unroll
    for (int j=0;j<DINP;j++){
        float a = e[j]*inv;
        if (edge) a *= edge[base+j];
        alpha[base+j] = a;
    }
}

__global__ void gat_agg_kernel(const float* __restrict__ alpha, const float* __restrict__ XP,
                               float* __restrict__ H)
{
    int b = blockIdx.x;
    __shared__ float al[DINP*DINP];
    for (int i=threadIdx.x;i<DINP*DINP;i+=blockDim.x) al[i]=alpha[(size_t)b*DINP*DINP+i];
    __syncthreads();
    const float* xp = XP + (size_t)b*DINP*FIN;
    float* hb = H + (size_t)b*DINP*FIN;
    for (int idx=threadIdx.x; idx<DINP*FIN; idx+=blockDim.x){
        int i = idx/FIN, c = idx%FIN;
        float s=0.f;
        #pragma unroll 6
        for (int j=0;j<DINP;j++) s += al[i*DINP+j]*xp[(size_t)j*FIN+c];
        hb[idx]=s;
    }
}

__global__ void sq_kernel(const float* __restrict__ A)
{
    int b = blockIdx.x; int t = threadIdx.x;
    float s=0.f;
    for (int i=t;i<DINP*DINP;i+=256){ float v=A[(size_t)b*DINP*DINP+i]; s+=v*v; }
    __shared__ float r[256];
    r[t]=s; __syncthreads();
    for (int o=128;o>0;o>>=1){ if(t<o) r[t]+=r[t+o]; __syncthreads(); }
    if (t==0) g_sq[b]=r[0];
}

__global__ void dist_kernel(const float* __restrict__ A)
{
    int i = blockIdx.x; int t = threadIdx.x;
    __shared__ float Ai[DINP*DINP];
    for (int c=t;c<DINP*DINP;c+=256) Ai[c]=A[(size_t)i*DINP*DINP+c];
    __syncthreads();
    float local=0.f;
    for (int j=t;j<BATCH;j+=256){
        const float* Aj = A + (size_t)j*DINP*DINP;
        float dot=0.f;
        for (int c=0;c<DINP*DINP;c++) dot += Ai[c]*Aj[c];
        float d2 = g_sq[i]+g_sq[j]-2.f*dot;
        d2 = fmaxf(d2, 0.f);
        local += sqrtf(d2 + 1e-12f);
    }
    __shared__ float r[256];
    r[t]=local; __syncthreads();
    for (int o=128;o>0;o>>=1){ if(t<o) r[t]+=r[t+o]; __syncthreads(); }
    if (t==0) g_part[i]=r[0];
}

__global__ void fin_dist_kernel(float* __restrict__ out, int out_size)
{
    if (threadIdx.x==0){
        float s=0.f;
        for (int i=0;i<BATCH;i++) s += g_part[i];
        if (out_size > BATCH*2) out[BATCH*2] = s / ((float)BATCH*(float)BATCH);
    }
}

// ---------------- transformer input ----------------
__global__ void build_out_kernel(const float* __restrict__ times)
{
    size_t n = (size_t)blockIdx.x*blockDim.x + threadIdx.x;
    const size_t total = (size_t)NROWS_TR*DT;
    if (n >= total) return;
    int d = (int)(n % DT);
    int b = (int)((n / DT) % BATCH);
    int s = (int)(n / ((size_t)DT*BATCH));
    float v;
    if (d < DMODEL) {
        v = g_bufA[((size_t)b*DINP + (d>>2))*FIN + s*4 + (d&3)];
    } else {
        int k = d - DMODEL;
        float tv = times[(size_t)s*BATCH + b];
        int kk = (k < 8) ? k : k-8;
        float ts = powf(215.0f, (float)kk/7.0f) * 100.0f;
        float sc = tv / ts;
        v = (k < 8) ? sinf(sc) : cosf(sc);
    }
    g_x[n] = v;
}

// ---------------- attention (K and V fully resident in smem) ----------------
#define ATTN_SMEM (2*S_LEN*DH*4)   // 68800 B
__global__ void attn_kernel(const float* __restrict__ qkv, const int* __restrict__ lengths,
                            float* __restrict__ out)
{
    extern __shared__ float smA[];
    float* Ks = smA;
    float* Vs = smA + S_LEN*DH;
    int b = blockIdx.x, h = blockIdx.y;
    int len = lengths[b];
    for (int i = threadIdx.x; i < S_LEN*DH; i += blockDim.x) {
        int t = i / DH, d = i % DH;
        size_t base = ((size_t)t*BATCH + b)*(3*DT) + h*DH + d;
        Ks[i] = qkv[base + DT];
        Vs[i] = qkv[base + 2*DT];
    }
    __syncthreads();
    int s = threadIdx.x;
    if (s >= S_LEN) return;
    float q[DH];
    {
        size_t qb = ((size_t)s*BATCH + b)*(3*DT) + h*DH;
        #pragma unroll
        for (int d=0; d<DH; d++) q[d] = qkv[qb + d];
    }
    const float scale = rsqrtf((float)DH);
    float m = -1e30f;
    for (int t=0; t<len; t++) {
        float sc = 0.f;
        #pragma unroll
        for (int d=0; d<DH; d++) sc += q[d]*Ks[t*DH+d];
        m = fmaxf(m, sc*scale);
    }
    float l = 0.f;
    float acc[DH];
    #pragma unroll
    for (int d=0; d<DH; d++) acc[d]=0.f;
    for (int t=0; t<len; t++) {
        float sc = 0.f;
        #pragma unroll
        for (int d=0; d<DH; d++) sc += q[d]*Ks[t*DH+d];
        float w = expf(sc*scale - m);
        l += w;
        #pragma unroll
        for (int d=0; d<DH; d++) acc[d] += w*Vs[t*DH+d];
    }
    float inv = 1.f/l;
    size_t ob = ((size_t)s*BATCH + b)*DT + h*DH;
    #pragma unroll
    for (int d=0; d<DH; d++) out[ob + d] = acc[d]*inv;
}

// ---------------- layernorm ----------------
__global__ void ln_kernel(const float* __restrict__ x, float* __restrict__ y,
                          const float* __restrict__ g, const float* __restrict__ bta)
{
    int row = blockIdx.x;
    const float* xr = x + (size_t)row*DT;
    int t = threadIdx.x;
    float v = xr[t];
    __shared__ float s1[DT], s2[DT];
    s1[t]=v; s2[t]=v*v; __syncthreads();
    if (t < 32) {
        float a=0.f, q=0.f;
        for (int i=t;i<DT;i+=32){ a+=s1[i]; q+=s2[i]; }
        for (int o=16;o>0;o>>=1){ a+=__shfl_down_sync(0xffffffff,a,o); q+=__shfl_down_sync(0xffffffff,q,o); }
        if (t==0){ s1[0]=a; s2[0]=q; }
    }
    __syncthreads();
    float mean = s1[0]/(float)DT;
    float var  = s2[0]/(float)DT - mean*mean;
    y[(size_t)row*DT + t] = (v-mean)*rsqrtf(var+1e-5f)*g[t] + bta[t];
}

// ---------------- pooled features + static embedding ----------------
__global__ void agg_emb_kernel(const int* __restrict__ lengths,
                               const float* __restrict__ statics,
                               const float* __restrict__ emb_w, const float* __restrict__ emb_b)
{
    int b = blockIdx.x; int d = threadIdx.x;
    int len = lengths[b];
    if (d < DT) {
        float s = 0.f;
        for (int t=0;t<len;t++) s += g_x[((size_t)t*BATCH + b)*DT + d];
        g_feat[b*DFINAL+d] = s / ((float)len + 1.0f);
    } else if (d < DFINAL) {
        int j = d - DT;
        float s = emb_b[j];
        #pragma unroll
        for (int r=0;r<9;r++) s += statics[b*9+r]*emb_w[r*DINP+j];
        g_feat[b*DFINAL+d] = s;
    }
}

// ---------------- final MLP ----------------
__global__ void mlp_kernel(const float* __restrict__ w1, const float* __restrict__ b1,
                           const float* __restrict__ w2, const float* __restrict__ b2,
                           float* __restrict__ out)
{
    int b = blockIdx.x; int t = threadIdx.x;
    __shared__ float f[DFINAL], hd[DFINAL];
    f[t] = g_feat[b*DFINAL+t];
    __syncthreads();
    float s = b1[t];
    for (int r=0;r<DFINAL;r++) s += f[r]*w1[r*DFINAL+t];
    hd[t] = fmaxf(s, 0.f);
    __syncthreads();
    if (t < 2) {
        float s2 = b2[t];
        for (int r=0;r<DFINAL;r++) s2 += hd[r]*w2[r*2+t];
        out[b*2+t] = s2;
    }
}

// ---------------- launch ----------------
extern "C" void kernel_launch(void* const* d_in, const int* in_sizes, int n_in,
                              void* d_out, int out_size)
{
    const float* src    = (const float*)d_in[0];
    const float* statics= (const float*)d_in[1];
    const float* times  = (const float*)d_in[2];
    const int*   lengths= (const int*)d_in[3];
    const float* R_u    = (const float*)d_in[4];
    const float* emb_w  = (const float*)d_in[5];
    const float* emb_b  = (const float*)d_in[6];
    const float* W1     = (const float*)d_in[7];
    const float* a1_s   = (const float*)d_in[8];
    const float* a1_d   = (const float*)d_in[9];
    const float* W2     = (const float*)d_in[10];
    const float* a2_s   = (const float*)d_in[11];
    const float* a2_d   = (const float*)d_in[12];
    const float* attn_in_w  = (const float*)d_in[13];
    const float* attn_in_b  = (const float*)d_in[14];
    const float* attn_out_w = (const float*)d_in[15];
    const float* attn_out_b = (const float*)d_in[16];
    const float* ff1_w  = (const float*)d_in[17];
    const float* ff1_b  = (const float*)d_in[18];
    const float* ff2_w  = (const float*)d_in[19];
    const float* ff2_b  = (const float*)d_in[20];
    const float* ln1_g  = (const float*)d_in[21];
    const float* ln1_b  = (const float*)d_in[22];
    const float* ln2_g  = (const float*)d_in[23];
    const float* ln2_b  = (const float*)d_in[24];
    const float* mlp1_w = (const float*)d_in[25];
    const float* mlp1_b = (const float*)d_in[26];
    const float* mlp2_w = (const float*)d_in[27];
    const float* mlp2_b = (const float*)d_in[28];
    float* out = (float*)d_out;

    float *bufA, *bufB, *al1, *al2, *x, *qkv, *att, *tmp, *ff;
    cudaGetSymbolAddress((void**)&bufA, g_bufA);
    cudaGetSymbolAddress((void**)&bufB, g_bufB);
    cudaGetSymbolAddress((void**)&al1,  g_alpha1);
    cudaGetSymbolAddress((void**)&al2,  g_alpha2);
    cudaGetSymbolAddress((void**)&x,    g_x);
    cudaGetSymbolAddress((void**)&qkv,  g_qkv);
    cudaGetSymbolAddress((void**)&att,  g_att);
    cudaGetSymbolAddress((void**)&tmp,  g_tmp);
    cudaGetSymbolAddress((void**)&ff,   g_ff);

    static bool attr_done = false;
    if (!attr_done) {
        cudaFuncSetAttribute(attn_kernel,
                             cudaFuncAttributeMaxDynamicSharedMemorySize, ATTN_SMEM);
        attr_done = true;
    }

    zero_kernel<<<(out_size+255)/256, 256>>>(out, out_size);

    // ----- GAT -----
    {
        size_t nx = (size_t)BATCH*DINP*FIN;
        build_x_kernel<<<(unsigned)((nx+255)/256), 256>>>(src, R_u);
        dim3 gg((FIN+127)/128, NROWS_GAT/128);
        hgemm_kernel<<<gg,256>>>(bufA, W1, bufB, NROWS_GAT, FIN, FIN, nullptr, nullptr, 0);
        psd_kernel<<<NROWS_GAT,256>>>(bufB, a1_s, a1_d);
        alpha_kernel<<<BATCH,64>>>(nullptr, al1);
        gat_agg_kernel<<<BATCH,256>>>(al1, bufB, bufA);
        hgemm_kernel<<<gg,256>>>(bufA, W2, bufB, NROWS_GAT, FIN, FIN, nullptr, nullptr, 0);
        psd_kernel<<<NROWS_GAT,256>>>(bufB, a2_s, a2_d);
        alpha_kernel<<<BATCH,64>>>(al1, al2);
        gat_agg_kernel<<<BATCH,256>>>(al2, bufB, bufA);
        sq_kernel<<<BATCH,256>>>(al2);
        dist_kernel<<<BATCH,256>>>(al2);
        fin_dist_kernel<<<1,32>>>(out, out_size);
    }

    // ----- transformer -----
    {
        size_t no = (size_t)NROWS_TR*DT;
        build_out_kernel<<<(unsigned)((no+255)/256), 256>>>(times);
        for (int l=0; l<2; l++) {
            dim3 gq((3*DT+127)/128, NROWS_TR/128);
            hgemm_kernel<<<gq,256>>>(x, attn_in_w + (size_t)l*DT*3*DT, qkv,
                                     NROWS_TR, 3*DT, DT, attn_in_b + l*3*DT, nullptr, 0);
            attn_kernel<<<dim3(BATCH,NHEAD),256,ATTN_SMEM>>>(qkv, lengths, att);
            dim3 gp((DT+127)/128, NROWS_TR/128);
            hgemm_kernel<<<gp,256>>>(att, attn_out_w + (size_t)l*DT*DT, tmp,
                                     NROWS_TR, DT, DT, attn_out_b + l*DT, x, 0);
            ln_kernel<<<NROWS_TR,DT>>>(tmp, x, ln1_g + l*DT, ln1_b + l*DT);
            dim3 gf1((NHID+127)/128, NROWS_TR/128);
            hgemm_kernel<<<gf1,256>>>(x, ff1_w + (size_t)l*DT*NHID, ff,
                                      NROWS_TR, NHID, DT, ff1_b + l*NHID, nullptr, 1);
            dim3 gf2((DT+127)/128, NROWS_TR/128);
            hgemm_kernel<<<gf2,256>>>(ff, ff2_w + (size_t)l*NHID*DT, tmp,
                                      NROWS_TR, DT, NHID, ff2_b + l*DT, x, 0);
            ln_kernel<<<NROWS_TR,DT>>>(tmp, x, ln2_g + l*DT, ln2_b + l*DT);
        }
    }

    // ----- head -----
    agg_emb_kernel<<<BATCH,DFINAL>>>(lengths, statics, emb_w, emb_b);
    mlp_kernel<<<BATCH,DFINAL>>>(mlp1_w, mlp1_b, mlp2_w, mlp2_b, out);
}